// round 11
// baseline (speedup 1.0000x reference)
#include <cuda_runtime.h>
#include <cstdint>

#define B 8
#define T 4096
#define D 1024
#define S 64
#define BOND 32
#define NQ 8
#define QDIM 256
#define NB 148          // one block per SM, co-resident (gbar-safe)
#define NT 1024

// ------- device scratch (no allocations allowed) -------
__device__ float g_part[2 * NB * D];     // two partial slots per block
__device__ float g_m0[B * 32];           // padded per batch
__device__ float g_m1[B * 32];
__device__ float g_overlaps[B * S];
__device__ float g_feats[S * NQ];
__device__ float g_fold[NQ * D];         // folded Wd (32 KB)
__device__ int   g_bar_count;            // zero-init
__device__ int   g_bar_gen;

// ---------------- software grid barrier (all NB blocks resident) ----------------
__device__ __forceinline__ void gbar() {
    __threadfence();
    __syncthreads();
    if (threadIdx.x == 0) {
        int gen = *(volatile int*)&g_bar_gen;
        if (atomicAdd(&g_bar_count, 1) == NB - 1) {
            *(volatile int*)&g_bar_count = 0;
            __threadfence();
            *(volatile int*)&g_bar_gen = gen + 1;
        } else {
            while (*(volatile int*)&g_bar_gen == gen) __nanosleep(64);
        }
    }
    __syncthreads();
}

// 32768 rows split: blocks 0..59 get 222 rows, 60..147 get 221
__device__ __forceinline__ int row_base(int k) { return k * 221 + (k < 60 ? k : 60); }
__device__ __forceinline__ int row_cnt(int k)  { return 221 + (k < 60 ? 1 : 0); }

__device__ __forceinline__ float4 ldcs4(const float4* p) {
    float4 v;
    asm volatile("ld.global.cs.v4.f32 {%0,%1,%2,%3}, [%4];"
                 : "=f"(v.x), "=f"(v.y), "=f"(v.z), "=f"(v.w) : "l"(p));
    return v;
}
__device__ __forceinline__ void stwt4(float4* p, float4 v) {
    asm volatile("st.global.wt.v4.f32 [%0], {%1,%2,%3,%4};"
                 :: "l"(p), "f"(v.x), "f"(v.y), "f"(v.z), "f"(v.w) : "memory");
}
__device__ __forceinline__ void stcg4(float4* p, float4 v) {
    asm volatile("st.global.cg.v4.f32 [%0], {%1,%2,%3,%4};"
                 :: "l"(p), "f"(v.x), "f"(v.y), "f"(v.z), "f"(v.w) : "memory");
}

__global__ void __launch_bounds__(NT, 1)
k_fused(const float* __restrict__ x,
        const float* __restrict__ Wq,
        const float* __restrict__ bq,
        const float* __restrict__ Wd,
        const float* __restrict__ bd,
        const float* __restrict__ cf,
        const float* __restrict__ cm,
        const float* __restrict__ cl,
        float* __restrict__ out) {
    __shared__ float smem[12288];   // 48 KB, aliased per phase
    const int blk = blockIdx.x;
    const int tid = threadIdx.x;
    const int col4 = tid & 255;
    const int rq = tid >> 8;        // row phase (0..3)

    // ========== Phase 1: column sums over contiguous row range (no inner barriers) ==========
    {
        const int base = row_base(blk);
        const int cnt  = row_cnt(blk);
        const int bnd  = min(cnt, (((base >> 12) + 1) << 12) - base);   // local batch split
        const float4* xp = reinterpret_cast<const float4*>(x) + (size_t)base * 256 + col4;
        float4 a0 = make_float4(0.f, 0.f, 0.f, 0.f);
        float4 a1 = make_float4(0.f, 0.f, 0.f, 0.f);
#pragma unroll 8
        for (int r = rq; r < cnt; r += 4) {
            float4 v = xp[(size_t)r * 256];
            if (r < bnd) { a0.x += v.x; a0.y += v.y; a0.z += v.z; a0.w += v.w; }
            else         { a1.x += v.x; a1.y += v.y; a1.z += v.z; a1.w += v.w; }
        }
        float4* sm4 = reinterpret_cast<float4*>(smem);
        sm4[rq * 256 + col4] = a0;
        __syncthreads();
        if (tid < 256) {
            float4 s0 = sm4[tid], s1 = sm4[256 + tid], s2 = sm4[512 + tid], s3 = sm4[768 + tid];
            s0.x = (s0.x + s1.x) + (s2.x + s3.x);
            s0.y = (s0.y + s1.y) + (s2.y + s3.y);
            s0.z = (s0.z + s1.z) + (s2.z + s3.z);
            s0.w = (s0.w + s1.w) + (s2.w + s3.w);
            stcg4(&reinterpret_cast<float4*>(g_part)[(blk * 2 + 0) * 256 + tid], s0);
        }
        __syncthreads();
        sm4[rq * 256 + col4] = a1;
        __syncthreads();
        if (tid < 256) {
            float4 s0 = sm4[tid], s1 = sm4[256 + tid], s2 = sm4[512 + tid], s3 = sm4[768 + tid];
            s0.x = (s0.x + s1.x) + (s2.x + s3.x);
            s0.y = (s0.y + s1.y) + (s2.y + s3.y);
            s0.z = (s0.z + s1.z) + (s2.z + s3.z);
            s0.w = (s0.w + s1.w) + (s2.w + s3.w);
            stcg4(&reinterpret_cast<float4*>(g_part)[(blk * 2 + 1) * 256 + tid], s0);
        }
    }
    gbar();

    // === Phase 2 window: query (0..7) | fold Wd (8..39) | preload cm (84..147) ===
    if (blk < B) {
        float* xs = smem;           // 1024
        float* pr = smem + 1024;    // 1024 (4 x 256)
        float* qa = smem + 2048;    // 256
        float* red = smem + 2304;   // 8
        const int b = blk;
        {   // gather tagged partial slots for batch b
            float acc = 0.f;
            for (int k = 0; k < NB; ++k) {
                const int bs = row_base(k);
                const int ct = row_cnt(k);
                const int t0 = bs >> 12;
                const int t1 = (bs + ct - 1) >> 12;
                if (t0 == b) acc += __ldcg(&g_part[(k * 2 + 0) * D + tid]);
                if (t1 == b && t1 != t0) acc += __ldcg(&g_part[(k * 2 + 1) * D + tid]);
            }
            xs[tid] = acc * (1.0f / (float)T);
        }
        __syncthreads();

        const int j = tid & 255;
        const int kc = tid >> 8;
        const int k0 = kc * 256;
        {
            float a = 0.f;
#pragma unroll 8
            for (int k = 0; k < 256; ++k)
                a = fmaf(xs[k0 + k], Wq[(size_t)(k0 + k) * QDIM + j], a);
            pr[kc * 256 + j] = a;
        }
        __syncthreads();

        float logit = 0.f;
        if (tid < QDIM)
            logit = (pr[j] + pr[256 + j]) + (pr[512 + j] + pr[768 + j]) + bq[j];

        // softmax over 256 — barriers uniform
        float m = logit;
#pragma unroll
        for (int o = 16; o; o >>= 1) m = fmaxf(m, __shfl_xor_sync(0xffffffffu, m, o));
        if (tid < QDIM && (tid & 31) == 0) red[tid >> 5] = m;
        __syncthreads();
        float bm = red[0];
#pragma unroll
        for (int i = 1; i < 8; ++i) bm = fmaxf(bm, red[i]);
        float e = (tid < QDIM) ? __expf(logit - bm) : 0.f;
        float ssum = e;
#pragma unroll
        for (int o = 16; o; o >>= 1) ssum += __shfl_xor_sync(0xffffffffu, ssum, o);
        __syncthreads();
        if (tid < QDIM && (tid & 31) == 0) red[tid >> 5] = ssum;
        __syncthreads();
        float tot = 0.f;
#pragma unroll
        for (int i = 0; i < 8; ++i) tot += red[i];
        if (tid < QDIM) qa[j] = e / tot;
        __syncthreads();

        if (tid < 16) {   // amplitude means, JAX OOB-clamp to index 255
            const int q = tid & 7;
            const bool one = tid >= 8;
            const int s = 1 << (7 - q);
            const int cin = min(s, 128 / s);
            float a = 0.f;
            const int off = one ? s : 0;
            for (int i = 0; i < cin; ++i) a += qa[i * 2 * s + off];
            a += (float)(s - cin) * qa[QDIM - 1];
            float* dst = one ? g_m1 : g_m0;
            dst[b * 32 + q] = a / (float)s;
        }
    } else if (blk < 40) {
        // fold[q][d] = sum_i Wd[i*8+q][d]
        if (tid < 256) {
            const int p = blk - 8;
            const int d = p * 32 + (tid >> 3);
            const int q = tid & 7;
            float acc = 0.f;
#pragma unroll 8
            for (int i = 0; i < 32; ++i)
                acc += Wd[(size_t)(i * 8 + q) * D + d];
            g_fold[q * D + d] = acc;
        }
    } else if (blk >= 84) {
        // coalesced preload of this slot's cm slice into smem
        const int s = blk - 84;
        const float4* src = reinterpret_cast<const float4*>(cm + (size_t)s * 12288);
        float4* dst = reinterpret_cast<float4*>(smem);
#pragma unroll
        for (int i = 0; i < 3; ++i)
            dst[i * 1024 + tid] = src[i * 1024 + tid];
    }
    gbar();

    // ============ Phase 3: slots (blocks 84..147; cm already in smem) ============
    if (blk >= 84) {
        const int s = blk - 84;
        if (tid < 256) {
            const int w = tid >> 5;
            const int lane = tid & 31;
            float fsum, inv_cnt;
            if (w == 0) {
                fsum = cf[s * 64 + lane] + cf[s * 64 + 32 + lane];
                inv_cnt = 1.0f / 64.0f;
            } else if (w == 7) {
                fsum = cl[s * 64 + lane] + cl[s * 64 + 32 + lane];
                inv_cnt = 1.0f / 64.0f;
            } else {
                const float* base = smem + (w - 1) * 2048;
                fsum = 0.f;
#pragma unroll
                for (int i = 0; i < 64; ++i) fsum += base[i * 32 + lane];
                inv_cnt = 1.0f / 2048.0f;
            }
#pragma unroll
            for (int o = 16; o; o >>= 1) fsum += __shfl_xor_sync(0xffffffffu, fsum, o);
            if (lane == 0) g_feats[s * NQ + w] = fsum * inv_cnt;

            const int b = w;   // batch = warp
            float M0[NQ], M1[NQ];
#pragma unroll
            for (int q = 0; q < NQ; ++q) {
                M0[q] = __ldcg(&g_m0[b * 32 + q]);
                M1[q] = __ldcg(&g_m1[b * 32 + q]);
            }
            float v = M0[0] * cf[s * 64 + lane] + M1[0] * cf[s * 64 + 32 + lane];
#pragma unroll
            for (int q = 1; q <= NQ - 2; ++q) {
                const float* base = smem + (q - 1) * 2048;
                float nv = 0.f;
#pragma unroll 8
                for (int l = 0; l < BOND; ++l) {
                    float vl = __shfl_sync(0xffffffffu, v, l);
                    float c0 = base[l * 64 + lane];
                    float c1 = base[l * 64 + 32 + lane];
                    nv = fmaf(vl, fmaf(M0[q], c0, M1[q] * c1), nv);
                }
                v = nv;
            }
            float wl = M0[NQ - 1] * cl[(s * BOND + lane) * 2] +
                       M1[NQ - 1] * cl[(s * BOND + lane) * 2 + 1];
            float ov = v * wl;
#pragma unroll
            for (int o = 16; o; o >>= 1) ov += __shfl_xor_sync(0xffffffffu, ov, o);
            if (lane == 0) g_overlaps[b * S + s] = ov;
        }
    }
    gbar();

    // ===== Phase 4: attention+gg (all batches), bias table, stream out = x + bias =====
    {
        float* s_bias = smem;          // 8 x 1024
        float* s_gg = smem + 8192;     // 64

        if (tid < 256) {   // warp w = batch w
            const int w = tid >> 5;
            const int lane = tid & 31;
            float a0 = __ldcg(&g_overlaps[w * S + lane]);
            float a1 = __ldcg(&g_overlaps[w * S + 32 + lane]);
            float m = fmaxf(a0, a1);
#pragma unroll
            for (int o = 16; o; o >>= 1) m = fmaxf(m, __shfl_xor_sync(0xffffffffu, m, o));
            float e0 = __expf(a0 - m);
            float e1 = __expf(a1 - m);
            float ssum = e0 + e1;
#pragma unroll
            for (int o = 16; o; o >>= 1) ssum += __shfl_xor_sync(0xffffffffu, ssum, o);
            const float inv = 1.0f / ssum;
            const float at0 = e0 * inv;
            const float at1 = e1 * inv;
#pragma unroll
            for (int q = 0; q < NQ; ++q) {
                float p = at0 * __ldcg(&g_feats[lane * NQ + q]) +
                          at1 * __ldcg(&g_feats[(32 + lane) * NQ + q]);
#pragma unroll
                for (int o = 16; o; o >>= 1) p += __shfl_xor_sync(0xffffffffu, p, o);
                if (lane == 0) s_gg[w * NQ + q] = p;
            }
        }
        __syncthreads();

        {   // bias table for all 8 batches
            float f[NQ];
#pragma unroll
            for (int q = 0; q < NQ; ++q) f[q] = __ldcg(&g_fold[q * D + tid]);
            const float bdd = bd[tid];
#pragma unroll
            for (int b = 0; b < B; ++b) {
                float acc = bdd;
#pragma unroll
                for (int q = 0; q < NQ; ++q)
                    acc = fmaf(s_gg[b * NQ + q], f[q], acc);
                s_bias[b * D + tid] = acc;
            }
        }
        __syncthreads();

        // stream own range in REVERSE row order (phase-1 tail is L2-hot), no barriers
        // x: ld.cs (evict-first, last use)   out: st.wt (no L2 allocation -> keep x resident)
        const int base = row_base(blk);
        const int cnt  = row_cnt(blk);
        const float4* xp = reinterpret_cast<const float4*>(x) + (size_t)base * 256 + col4;
        float4* op = reinterpret_cast<float4*>(out) + (size_t)base * 256 + col4;
        const float4* bias4p = reinterpret_cast<const float4*>(s_bias);
        const int rmax = rq + ((cnt - 1 - rq) / 4) * 4;   // largest r ≡ rq (mod 4), < cnt
#pragma unroll 8
        for (int r = rmax; r >= 0; r -= 4) {
            const int b = (base + r) >> 12;
            const float4 bias4 = bias4p[b * 256 + col4];
            float4 v = ldcs4(&xp[(size_t)r * 256]);
            v.x += bias4.x; v.y += bias4.y; v.z += bias4.z; v.w += bias4.w;
            stwt4(&op[(size_t)r * 256], v);
        }
    }
}

extern "C" void kernel_launch(void* const* d_in, const int* in_sizes, int n_in,
                              void* d_out, int out_size) {
    const float* x  = (const float*)d_in[0];
    const float* Wq = (const float*)d_in[1];
    const float* bq = (const float*)d_in[2];
    const float* Wd = (const float*)d_in[3];
    const float* bd = (const float*)d_in[4];
    const float* cf = (const float*)d_in[5];
    const float* cm = (const float*)d_in[6];
    const float* cl = (const float*)d_in[7];
    float* out = (float*)d_out;

    k_fused<<<NB, NT>>>(x, Wq, bq, Wd, bd, cf, cm, cl, out);
}

// round 12
// speedup vs baseline: 1.1647x; 1.1647x over previous
#include <cuda_runtime.h>
#include <cstdint>

#define B 8
#define T 4096
#define D 1024
#define S 64
#define BOND 32
#define NQ 8
#define QDIM 256
#define NB 148          // kernel-1 blocks: one per SM, co-resident (gbar-safe)
#define NT 1024

// ------- device scratch (no allocations allowed) -------
__device__ float g_part[2 * NB * D];     // two partial slots per block
__device__ float g_m0[B * 32];           // padded per batch
__device__ float g_m1[B * 32];
__device__ float g_overlaps[B * S];
__device__ float g_feats[S * NQ];
__device__ float g_fold[NQ * D];         // folded Wd (32 KB)
__device__ float g_bias[B * D];          // final per-batch bias rows
__device__ int   g_bar_count;            // zero-init
__device__ int   g_bar_gen;

// ---------------- software grid barrier (all NB blocks resident) ----------------
__device__ __forceinline__ void gbar() {
    __threadfence();
    __syncthreads();
    if (threadIdx.x == 0) {
        int gen = *(volatile int*)&g_bar_gen;
        if (atomicAdd(&g_bar_count, 1) == NB - 1) {
            *(volatile int*)&g_bar_count = 0;
            __threadfence();
            *(volatile int*)&g_bar_gen = gen + 1;
        } else {
            while (*(volatile int*)&g_bar_gen == gen) __nanosleep(64);
        }
    }
    __syncthreads();
}

// 32768 rows split: blocks 0..59 get 222 rows, 60..147 get 221
__device__ __forceinline__ int row_base(int k) { return k * 221 + (k < 60 ? k : 60); }
__device__ __forceinline__ int row_cnt(int k)  { return 221 + (k < 60 ? 1 : 0); }

// ===================== Kernel 1: reduce + query + slots + bias table =====================
__global__ void __launch_bounds__(NT, 1)
k_head(const float* __restrict__ x,
       const float* __restrict__ Wq,
       const float* __restrict__ bq,
       const float* __restrict__ Wd,
       const float* __restrict__ bd,
       const float* __restrict__ cf,
       const float* __restrict__ cm,
       const float* __restrict__ cl) {
    __shared__ float smem[12288];   // 48 KB, aliased per phase
    const int blk = blockIdx.x;
    const int tid = threadIdx.x;
    const int col4 = tid & 255;
    const int rq = tid >> 8;        // row phase (0..3)

    // ========== Phase 1: column sums over contiguous row range (no inner barriers) ==========
    {
        const int base = row_base(blk);
        const int cnt  = row_cnt(blk);
        const int bnd  = min(cnt, (((base >> 12) + 1) << 12) - base);   // local batch split
        const float4* xp = reinterpret_cast<const float4*>(x) + (size_t)base * 256 + col4;
        float4 a0 = make_float4(0.f, 0.f, 0.f, 0.f);
        float4 a1 = make_float4(0.f, 0.f, 0.f, 0.f);
#pragma unroll 8
        for (int r = rq; r < cnt; r += 4) {
            float4 v = xp[(size_t)r * 256];
            if (r < bnd) { a0.x += v.x; a0.y += v.y; a0.z += v.z; a0.w += v.w; }
            else         { a1.x += v.x; a1.y += v.y; a1.z += v.z; a1.w += v.w; }
        }
        float4* sm4 = reinterpret_cast<float4*>(smem);
        sm4[rq * 256 + col4] = a0;
        __syncthreads();
        if (tid < 256) {
            float4 s0 = sm4[tid], s1 = sm4[256 + tid], s2 = sm4[512 + tid], s3 = sm4[768 + tid];
            s0.x = (s0.x + s1.x) + (s2.x + s3.x);
            s0.y = (s0.y + s1.y) + (s2.y + s3.y);
            s0.z = (s0.z + s1.z) + (s2.z + s3.z);
            s0.w = (s0.w + s1.w) + (s2.w + s3.w);
            reinterpret_cast<float4*>(g_part)[(blk * 2 + 0) * 256 + tid] = s0;
        }
        __syncthreads();
        sm4[rq * 256 + col4] = a1;
        __syncthreads();
        if (tid < 256) {
            float4 s0 = sm4[tid], s1 = sm4[256 + tid], s2 = sm4[512 + tid], s3 = sm4[768 + tid];
            s0.x = (s0.x + s1.x) + (s2.x + s3.x);
            s0.y = (s0.y + s1.y) + (s2.y + s3.y);
            s0.z = (s0.z + s1.z) + (s2.z + s3.z);
            s0.w = (s0.w + s1.w) + (s2.w + s3.w);
            reinterpret_cast<float4*>(g_part)[(blk * 2 + 1) * 256 + tid] = s0;
        }
    }
    gbar();

    // === Phase 2 window: query (0..7) | fold Wd (8..39) | preload cm (84..147) ===
    if (blk < B) {
        float* xs = smem;           // 1024
        float* pr = smem + 1024;    // 1024 (4 x 256)
        float* qa = smem + 2048;    // 256
        float* red = smem + 2304;   // 8
        const int b = blk;
        {   // gather tagged partial slots for batch b
            float acc = 0.f;
            for (int k = 0; k < NB; ++k) {
                const int bs = row_base(k);
                const int ct = row_cnt(k);
                const int t0 = bs >> 12;
                const int t1 = (bs + ct - 1) >> 12;
                if (t0 == b) acc += g_part[(k * 2 + 0) * D + tid];
                if (t1 == b && t1 != t0) acc += g_part[(k * 2 + 1) * D + tid];
            }
            xs[tid] = acc * (1.0f / (float)T);
        }
        __syncthreads();

        const int j = tid & 255;
        const int kc = tid >> 8;
        const int k0 = kc * 256;
        {
            float a = 0.f;
#pragma unroll 8
            for (int k = 0; k < 256; ++k)
                a = fmaf(xs[k0 + k], Wq[(size_t)(k0 + k) * QDIM + j], a);
            pr[kc * 256 + j] = a;
        }
        __syncthreads();

        float logit = 0.f;
        if (tid < QDIM)
            logit = (pr[j] + pr[256 + j]) + (pr[512 + j] + pr[768 + j]) + bq[j];

        // softmax over 256 — barriers uniform
        float m = logit;
#pragma unroll
        for (int o = 16; o; o >>= 1) m = fmaxf(m, __shfl_xor_sync(0xffffffffu, m, o));
        if (tid < QDIM && (tid & 31) == 0) red[tid >> 5] = m;
        __syncthreads();
        float bm = red[0];
#pragma unroll
        for (int i = 1; i < 8; ++i) bm = fmaxf(bm, red[i]);
        float e = (tid < QDIM) ? __expf(logit - bm) : 0.f;
        float ssum = e;
#pragma unroll
        for (int o = 16; o; o >>= 1) ssum += __shfl_xor_sync(0xffffffffu, ssum, o);
        __syncthreads();
        if (tid < QDIM && (tid & 31) == 0) red[tid >> 5] = ssum;
        __syncthreads();
        float tot = 0.f;
#pragma unroll
        for (int i = 0; i < 8; ++i) tot += red[i];
        if (tid < QDIM) qa[j] = e / tot;
        __syncthreads();

        if (tid < 16) {   // amplitude means, JAX OOB-clamp to index 255
            const int q = tid & 7;
            const bool one = tid >= 8;
            const int s = 1 << (7 - q);
            const int cin = min(s, 128 / s);
            float a = 0.f;
            const int off = one ? s : 0;
            for (int i = 0; i < cin; ++i) a += qa[i * 2 * s + off];
            a += (float)(s - cin) * qa[QDIM - 1];
            float* dst = one ? g_m1 : g_m0;
            dst[b * 32 + q] = a / (float)s;
        }
    } else if (blk < 40) {
        // fold[q][d] = sum_i Wd[i*8+q][d]
        if (tid < 256) {
            const int p = blk - 8;
            const int d = p * 32 + (tid >> 3);
            const int q = tid & 7;
            float acc = 0.f;
#pragma unroll 8
            for (int i = 0; i < 32; ++i)
                acc += Wd[(size_t)(i * 8 + q) * D + d];
            g_fold[q * D + d] = acc;
        }
    } else if (blk >= 84) {
        // coalesced preload of this slot's cm slice into smem
        const int s = blk - 84;
        const float4* src = reinterpret_cast<const float4*>(cm + (size_t)s * 12288);
        float4* dst = reinterpret_cast<float4*>(smem);
#pragma unroll
        for (int i = 0; i < 3; ++i)
            dst[i * 1024 + tid] = src[i * 1024 + tid];
    }
    gbar();

    // ============ Phase 3: slots (blocks 84..147; cm already in smem) ============
    if (blk >= 84) {
        const int s = blk - 84;
        if (tid < 256) {
            const int w = tid >> 5;
            const int lane = tid & 31;
            float fsum, inv_cnt;
            if (w == 0) {
                fsum = cf[s * 64 + lane] + cf[s * 64 + 32 + lane];
                inv_cnt = 1.0f / 64.0f;
            } else if (w == 7) {
                fsum = cl[s * 64 + lane] + cl[s * 64 + 32 + lane];
                inv_cnt = 1.0f / 64.0f;
            } else {
                const float* base = smem + (w - 1) * 2048;
                fsum = 0.f;
#pragma unroll
                for (int i = 0; i < 64; ++i) fsum += base[i * 32 + lane];
                inv_cnt = 1.0f / 2048.0f;
            }
#pragma unroll
            for (int o = 16; o; o >>= 1) fsum += __shfl_xor_sync(0xffffffffu, fsum, o);
            if (lane == 0) g_feats[s * NQ + w] = fsum * inv_cnt;

            const int b = w;   // batch = warp
            float M0[NQ], M1[NQ];
#pragma unroll
            for (int q = 0; q < NQ; ++q) {
                M0[q] = __ldcg(&g_m0[b * 32 + q]);
                M1[q] = __ldcg(&g_m1[b * 32 + q]);
            }
            float v = M0[0] * cf[s * 64 + lane] + M1[0] * cf[s * 64 + 32 + lane];
#pragma unroll
            for (int q = 1; q <= NQ - 2; ++q) {
                const float* base = smem + (q - 1) * 2048;
                float nv = 0.f;
#pragma unroll 8
                for (int l = 0; l < BOND; ++l) {
                    float vl = __shfl_sync(0xffffffffu, v, l);
                    float c0 = base[l * 64 + lane];
                    float c1 = base[l * 64 + 32 + lane];
                    nv = fmaf(vl, fmaf(M0[q], c0, M1[q] * c1), nv);
                }
                v = nv;
            }
            float wl = M0[NQ - 1] * cl[(s * BOND + lane) * 2] +
                       M1[NQ - 1] * cl[(s * BOND + lane) * 2 + 1];
            float ov = v * wl;
#pragma unroll
            for (int o = 16; o; o >>= 1) ov += __shfl_xor_sync(0xffffffffu, ov, o);
            if (lane == 0) g_overlaps[b * S + s] = ov;
        }
    }
    gbar();

    // ===== Phase 4: blocks 0..7 — attention + gg for batch b, write bias row =====
    if (blk < B) {
        const int b = blk;
        float* s_gg = smem;   // 8

        if (tid < 32) {
            const int lane = tid;
            float a0 = __ldcg(&g_overlaps[b * S + lane]);
            float a1 = __ldcg(&g_overlaps[b * S + 32 + lane]);
            float m = fmaxf(a0, a1);
#pragma unroll
            for (int o = 16; o; o >>= 1) m = fmaxf(m, __shfl_xor_sync(0xffffffffu, m, o));
            float e0 = __expf(a0 - m);
            float e1 = __expf(a1 - m);
            float ssum = e0 + e1;
#pragma unroll
            for (int o = 16; o; o >>= 1) ssum += __shfl_xor_sync(0xffffffffu, ssum, o);
            const float inv = 1.0f / ssum;
            const float at0 = e0 * inv;
            const float at1 = e1 * inv;
#pragma unroll
            for (int q = 0; q < NQ; ++q) {
                float p = at0 * __ldcg(&g_feats[lane * NQ + q]) +
                          at1 * __ldcg(&g_feats[(32 + lane) * NQ + q]);
#pragma unroll
                for (int o = 16; o; o >>= 1) p += __shfl_xor_sync(0xffffffffu, p, o);
                if (lane == 0) s_gg[q] = p;
            }
        }
        __syncthreads();

        float acc = bd[tid];
#pragma unroll
        for (int q = 0; q < NQ; ++q)
            acc = fmaf(s_gg[q], __ldcg(&g_fold[q * D + tid]), acc);
        g_bias[b * D + tid] = acc;
    }
}

// ===================== Kernel 2: out = x + bias (R3's proven k_add) =====================
__global__ void k_add(const float* __restrict__ x, float* __restrict__ out) {
    const int blk = blockIdx.x;
    const int b = blk >> 10;               // 1024 blocks per batch
    const size_t row0 = (size_t)blk * 4;
    const int tid = threadIdx.x;
    const float4 bias = reinterpret_cast<const float4*>(g_bias)[b * (D / 4) + tid];
    const float4* xp = reinterpret_cast<const float4*>(x) + row0 * (D / 4);
    float4* op = reinterpret_cast<float4*>(out) + row0 * (D / 4);
#pragma unroll
    for (int r = 0; r < 4; ++r) {
        float4 v = xp[r * (D / 4) + tid];
        v.x += bias.x; v.y += bias.y; v.z += bias.z; v.w += bias.w;
        op[r * (D / 4) + tid] = v;
    }
}

extern "C" void kernel_launch(void* const* d_in, const int* in_sizes, int n_in,
                              void* d_out, int out_size) {
    const float* x  = (const float*)d_in[0];
    const float* Wq = (const float*)d_in[1];
    const float* bq = (const float*)d_in[2];
    const float* Wd = (const float*)d_in[3];
    const float* bd = (const float*)d_in[4];
    const float* cf = (const float*)d_in[5];
    const float* cm = (const float*)d_in[6];
    const float* cl = (const float*)d_in[7];
    float* out = (float*)d_out;

    k_head<<<NB, NT>>>(x, Wq, bq, Wd, bd, cf, cm, cl);
    k_add<<<(B * T) / 4, 256>>>(x, out);
}